// round 12
// baseline (speedup 1.0000x reference)
#include <cuda_runtime.h>
#include <cuda_bf16.h>
#include <cstdint>

#define F_IN   128
#define F_HID  32
#define F_OUT  64
#define NDEG   11
#define MAXDEG 10
#define MAXN   100000
#define MAXE   1600000

// ---- scratch (__device__ globals; no allocation allowed) ----
__device__ int    g_is64;
__device__ int    g_deg[MAXN];
__device__ int    g_rowstart[MAXN];
__device__ int    g_cursor[MAXN];
__device__ int    g_csrc[MAXE];
__device__ int    g_bsum[256];
__device__ float  g_h2[MAXN * F_HID];    // relu(layer-1 out)
// packed weights: [d][k/4][o] as float4 over the 4 k-components
__device__ float4 g_W1p [NDEG * 32 * 32];
__device__ float4 g_Wr1p[NDEG * 32 * 32];
__device__ float4 g_W2p [NDEG * 8  * 64];
__device__ float4 g_Wr2p[NDEG * 8  * 64];

// edge_index may be int32 (jax default) or int64 (x64 enabled). Branch on flag.
__device__ __forceinline__ int edge_at(const void* ei, long long pos) {
    if (g_is64) return (int)((const long long*)ei)[pos];
    return ((const int*)ei)[pos];
}

// ---- zero + dtype sniff fused ----
__global__ void zero_detect_kernel(const void* ei, int N) {
    int i = blockIdx.x * blockDim.x + threadIdx.x;
    if (i < N) { g_deg[i] = 0; g_cursor[i] = 0; }
    if (blockIdx.x == 0 && threadIdx.x == 0) {
        const int* p = (const int*)ei;
        int zeros = 0;
#pragma unroll
        for (int j = 0; j < 32; j++)
            if (p[2 * j + 1] == 0) zeros++;
        g_is64 = (zeros >= 30) ? 1 : 0;
    }
}

// ---- repack weights into k-grouped float4 layout (tiny) ----
__global__ void repack_kernel(const float* __restrict__ W1, const float* __restrict__ Wr1,
                              const float* __restrict__ W2, const float* __restrict__ Wr2) {
    const int n1 = NDEG * 32 * 32;  // 11264
    const int n2 = NDEG * 8 * 64;   // 5632
    int t = blockIdx.x * blockDim.x + threadIdx.x;
    if (t < 2 * n1) {
        int u = (t < n1) ? t : t - n1;
        const float* src = (t < n1) ? W1 : Wr1;
        float4* dst = (t < n1) ? g_W1p : g_Wr1p;
        int d = u / 1024, r = u % 1024, g = r / 32, o = r % 32;
        int b = d * F_IN * F_HID + (4 * g) * F_HID + o;
        dst[u] = make_float4(src[b], src[b + F_HID], src[b + 2 * F_HID], src[b + 3 * F_HID]);
    } else if (t < 2 * n1 + 2 * n2) {
        int v = t - 2 * n1;
        int u = (v < n2) ? v : v - n2;
        const float* src = (v < n2) ? W2 : Wr2;
        float4* dst = (v < n2) ? g_W2p : g_Wr2p;
        int d = u / 512, r = u % 512, g = r / 64, o = r % 64;
        int b = d * F_HID * F_OUT + (4 * g) * F_OUT + o;
        dst[u] = make_float4(src[b], src[b + F_OUT], src[b + 2 * F_OUT], src[b + 3 * F_OUT]);
    }
}

// ---- degree count: int REDs only ----
__global__ void count_kernel(const void* __restrict__ ei, int E, int N) {
    int e = blockIdx.x * blockDim.x + threadIdx.x;
    if (e >= E) return;
    int dst = edge_at(ei, (long long)E + e);
    if ((unsigned)dst >= (unsigned)N) return;  // defensive
    atomicAdd(&g_deg[dst], 1);
}

// ---- exclusive scan of g_deg -> g_rowstart (3 stages) ----
__global__ void scan1_kernel(int N) {
    __shared__ int s[1024];
    int i = blockIdx.x * 1024 + threadIdx.x;
    int v = (i < N) ? g_deg[i] : 0;
    s[threadIdx.x] = v;
    __syncthreads();
    for (int off = 1; off < 1024; off <<= 1) {
        int t = (threadIdx.x >= off) ? s[threadIdx.x - off] : 0;
        __syncthreads();
        s[threadIdx.x] += t;
        __syncthreads();
    }
    if (i < N) g_rowstart[i] = s[threadIdx.x] - v;  // exclusive
    if (threadIdx.x == 1023) g_bsum[blockIdx.x] = s[1023];
}

__global__ void scan2_kernel(int nb) {
    __shared__ int s[256];
    int v = (threadIdx.x < nb) ? g_bsum[threadIdx.x] : 0;
    s[threadIdx.x] = v;
    __syncthreads();
    for (int off = 1; off < 256; off <<= 1) {
        int t = (threadIdx.x >= off) ? s[threadIdx.x - off] : 0;
        __syncthreads();
        s[threadIdx.x] += t;
        __syncthreads();
    }
    if (threadIdx.x < nb) g_bsum[threadIdx.x] = s[threadIdx.x] - v;  // exclusive
}

__global__ void scan3_kernel(int N) {
    int i = blockIdx.x * blockDim.x + threadIdx.x;
    if (i < N) g_rowstart[i] += g_bsum[i >> 10];
}

// ---- CSR fill ----
__global__ void fill_kernel(const void* __restrict__ ei, int E, int N) {
    int e = blockIdx.x * blockDim.x + threadIdx.x;
    if (e >= E) return;
    int src = edge_at(ei, e);
    int dst = edge_at(ei, (long long)E + e);
    if ((unsigned)dst >= (unsigned)N || (unsigned)src >= (unsigned)N) return;  // defensive
    int pos = atomicAdd(&g_cursor[dst], 1);
    g_csrc[g_rowstart[dst] + pos] = src;
}

// ---- fused layer-1: warp per 4 nodes; gather to smem, GEMV with 4x weight reuse ----
__global__ void layer1_kernel(const float* __restrict__ x, const float* __restrict__ b1, int N) {
    __shared__ float sh[8][4][256];  // per warp, per node: h[128] | x[128]  (32KB)
    int warp = threadIdx.x >> 5, lane = threadIdx.x & 31;
    int base = blockIdx.x * 32 + warp * 4;
    const float4* xv = (const float4*)x;

    int dcs[4];
#pragma unroll
    for (int i = 0; i < 4; i++) {
        int n = base + i;
        if (n >= N) { dcs[i] = -1; continue; }
        int d = g_deg[n];
        int start = g_rowstart[n];
        float4 hacc = make_float4(0.f, 0.f, 0.f, 0.f);
        int k = 0;
        for (; k + 8 <= d; k += 8) {
            int s0 = g_csrc[start + k + 0];
            int s1 = g_csrc[start + k + 1];
            int s2 = g_csrc[start + k + 2];
            int s3 = g_csrc[start + k + 3];
            int s4 = g_csrc[start + k + 4];
            int s5 = g_csrc[start + k + 5];
            int s6 = g_csrc[start + k + 6];
            int s7 = g_csrc[start + k + 7];
            float4 v0 = xv[(size_t)s0 * 32 + lane];
            float4 v1 = xv[(size_t)s1 * 32 + lane];
            float4 v2 = xv[(size_t)s2 * 32 + lane];
            float4 v3 = xv[(size_t)s3 * 32 + lane];
            float4 v4 = xv[(size_t)s4 * 32 + lane];
            float4 v5 = xv[(size_t)s5 * 32 + lane];
            float4 v6 = xv[(size_t)s6 * 32 + lane];
            float4 v7 = xv[(size_t)s7 * 32 + lane];
            hacc.x += ((v0.x + v1.x) + (v2.x + v3.x)) + ((v4.x + v5.x) + (v6.x + v7.x));
            hacc.y += ((v0.y + v1.y) + (v2.y + v3.y)) + ((v4.y + v5.y) + (v6.y + v7.y));
            hacc.z += ((v0.z + v1.z) + (v2.z + v3.z)) + ((v4.z + v5.z) + (v6.z + v7.z));
            hacc.w += ((v0.w + v1.w) + (v2.w + v3.w)) + ((v4.w + v5.w) + (v6.w + v7.w));
        }
        for (; k < d; k++) {
            int s = g_csrc[start + k];
            float4 v = xv[(size_t)s * 32 + lane];
            hacc.x += v.x; hacc.y += v.y; hacc.z += v.z; hacc.w += v.w;
        }
        ((float4*)&sh[warp][i][0])[lane]   = hacc;
        ((float4*)&sh[warp][i][128])[lane] = xv[(size_t)n * 32 + lane];
        dcs[i] = min(d, MAXDEG);
    }
    __syncwarp();

    if (dcs[0] >= 0 && dcs[0] == dcs[1] && dcs[1] == dcs[2] && dcs[2] == dcs[3]) {
        // fast path: one weight stream feeds all 4 nodes
        int dc = dcs[0];
        float bias = b1[dc * F_HID + lane];
        float a0 = bias, a1 = bias, a2 = bias, a3 = bias;
        const float4* w1 = &g_W1p [dc * 1024 + lane];
        const float4* wr = &g_Wr1p[dc * 1024 + lane];
#pragma unroll 4
        for (int g = 0; g < 32; g++) {
            float4 a = w1[g * 32];
            float4 b = wr[g * 32];
#pragma unroll
            for (int i = 0; i < 4; i++) {
                float4 hh = *(const float4*)&sh[warp][i][4 * g];
                float4 xx = *(const float4*)&sh[warp][i][128 + 4 * g];
                float t = hh.x * a.x + hh.y * a.y + hh.z * a.z + hh.w * a.w
                        + xx.x * b.x + xx.y * b.y + xx.z * b.z + xx.w * b.w;
                if (i == 0) a0 += t; else if (i == 1) a1 += t; else if (i == 2) a2 += t; else a3 += t;
            }
        }
        g_h2[(size_t)(base + 0) * F_HID + lane] = fmaxf(a0, 0.f);
        g_h2[(size_t)(base + 1) * F_HID + lane] = fmaxf(a1, 0.f);
        g_h2[(size_t)(base + 2) * F_HID + lane] = fmaxf(a2, 0.f);
        g_h2[(size_t)(base + 3) * F_HID + lane] = fmaxf(a3, 0.f);
    } else {
#pragma unroll
        for (int i = 0; i < 4; i++) {
            if (dcs[i] < 0) continue;
            int dc = dcs[i];
            float acc = b1[dc * F_HID + lane];
            const float4* w1 = &g_W1p [dc * 1024 + lane];
            const float4* wr = &g_Wr1p[dc * 1024 + lane];
#pragma unroll 8
            for (int g = 0; g < 32; g++) {
                float4 hh = *(const float4*)&sh[warp][i][4 * g];
                float4 xx = *(const float4*)&sh[warp][i][128 + 4 * g];
                float4 a = w1[g * 32];
                float4 b = wr[g * 32];
                acc += hh.x * a.x + hh.y * a.y + hh.z * a.z + hh.w * a.w
                     + xx.x * b.x + xx.y * b.y + xx.z * b.z + xx.w * b.w;
            }
            g_h2[(size_t)(base + i) * F_HID + lane] = fmaxf(acc, 0.f);
        }
    }
}

// ---- fused layer-2: warp per 4 nodes; gather + GEMV with 4x weight reuse ----
__global__ void layer2_kernel(const float* __restrict__ b2, float* __restrict__ out, int N) {
    __shared__ float sh[8][4][64];  // per warp, per node: agg[32] | h2[32]  (8KB)
    int warp = threadIdx.x >> 5, lane = threadIdx.x & 31;
    int base = blockIdx.x * 32 + warp * 4;

    int dcs[4];
#pragma unroll
    for (int i = 0; i < 4; i++) {
        int n = base + i;
        if (n >= N) { dcs[i] = -1; continue; }
        int d = g_deg[n];
        int start = g_rowstart[n];
        float hacc = 0.f;
        int k = 0;
        for (; k + 8 <= d; k += 8) {
            int s0 = g_csrc[start + k + 0];
            int s1 = g_csrc[start + k + 1];
            int s2 = g_csrc[start + k + 2];
            int s3 = g_csrc[start + k + 3];
            int s4 = g_csrc[start + k + 4];
            int s5 = g_csrc[start + k + 5];
            int s6 = g_csrc[start + k + 6];
            int s7 = g_csrc[start + k + 7];
            float v0 = g_h2[(size_t)s0 * F_HID + lane];
            float v1 = g_h2[(size_t)s1 * F_HID + lane];
            float v2 = g_h2[(size_t)s2 * F_HID + lane];
            float v3 = g_h2[(size_t)s3 * F_HID + lane];
            float v4 = g_h2[(size_t)s4 * F_HID + lane];
            float v5 = g_h2[(size_t)s5 * F_HID + lane];
            float v6 = g_h2[(size_t)s6 * F_HID + lane];
            float v7 = g_h2[(size_t)s7 * F_HID + lane];
            hacc += ((v0 + v1) + (v2 + v3)) + ((v4 + v5) + (v6 + v7));
        }
        for (; k < d; k++) {
            int s = g_csrc[start + k];
            hacc += g_h2[(size_t)s * F_HID + lane];
        }
        sh[warp][i][lane]      = hacc;
        sh[warp][i][32 + lane] = g_h2[(size_t)n * F_HID + lane];
        dcs[i] = min(d, MAXDEG);
    }
    __syncwarp();

    if (dcs[0] >= 0 && dcs[0] == dcs[1] && dcs[1] == dcs[2] && dcs[2] == dcs[3]) {
        int dc = dcs[0];
        float blo = b2[dc * F_OUT + lane];
        float bhi = b2[dc * F_OUT + 32 + lane];
        float acc0[4], acc1[4];
#pragma unroll
        for (int i = 0; i < 4; i++) { acc0[i] = blo; acc1[i] = bhi; }
        const float4* w2  = &g_W2p [dc * 512];
        const float4* wr2 = &g_Wr2p[dc * 512];
#pragma unroll
        for (int g = 0; g < 8; g++) {
            float4 a0 = w2 [g * 64 + lane];
            float4 a1 = w2 [g * 64 + 32 + lane];
            float4 r0 = wr2[g * 64 + lane];
            float4 r1 = wr2[g * 64 + 32 + lane];
#pragma unroll
            for (int i = 0; i < 4; i++) {
                float4 hh = *(const float4*)&sh[warp][i][4 * g];
                float4 xx = *(const float4*)&sh[warp][i][32 + 4 * g];
                acc0[i] += hh.x * a0.x + hh.y * a0.y + hh.z * a0.z + hh.w * a0.w
                         + xx.x * r0.x + xx.y * r0.y + xx.z * r0.z + xx.w * r0.w;
                acc1[i] += hh.x * a1.x + hh.y * a1.y + hh.z * a1.z + hh.w * a1.w
                         + xx.x * r1.x + xx.y * r1.y + xx.z * r1.z + xx.w * r1.w;
            }
        }
#pragma unroll
        for (int i = 0; i < 4; i++) {
            out[(size_t)(base + i) * F_OUT + lane]      = acc0[i];
            out[(size_t)(base + i) * F_OUT + 32 + lane] = acc1[i];
        }
    } else {
#pragma unroll
        for (int i = 0; i < 4; i++) {
            if (dcs[i] < 0) continue;
            int dc = dcs[i];
            float acc0 = b2[dc * F_OUT + lane];
            float acc1 = b2[dc * F_OUT + 32 + lane];
            const float4* w2  = &g_W2p [dc * 512];
            const float4* wr2 = &g_Wr2p[dc * 512];
#pragma unroll
            for (int g = 0; g < 8; g++) {
                float4 hh = *(const float4*)&sh[warp][i][4 * g];
                float4 xx = *(const float4*)&sh[warp][i][32 + 4 * g];
                float4 a0 = w2 [g * 64 + lane];
                float4 a1 = w2 [g * 64 + 32 + lane];
                float4 r0 = wr2[g * 64 + lane];
                float4 r1 = wr2[g * 64 + 32 + lane];
                acc0 += hh.x * a0.x + hh.y * a0.y + hh.z * a0.z + hh.w * a0.w
                      + xx.x * r0.x + xx.y * r0.y + xx.z * r0.z + xx.w * r0.w;
                acc1 += hh.x * a1.x + hh.y * a1.y + hh.z * a1.z + hh.w * a1.w
                      + xx.x * r1.x + xx.y * r1.y + xx.z * r1.z + xx.w * r1.w;
            }
            out[(size_t)(base + i) * F_OUT + lane]      = acc0;
            out[(size_t)(base + i) * F_OUT + 32 + lane] = acc1;
        }
    }
}

extern "C" void kernel_launch(void* const* d_in, const int* in_sizes, int n_in,
                              void* d_out, int out_size) {
    const float* x   = (const float*)d_in[0];
    const void*  ei  = d_in[1];
    const float* W1  = (const float*)d_in[2];
    const float* b1  = (const float*)d_in[3];
    const float* Wr1 = (const float*)d_in[4];
    const float* W2  = (const float*)d_in[5];
    const float* b2  = (const float*)d_in[6];
    const float* Wr2 = (const float*)d_in[7];

    int N = in_sizes[0] / F_IN;
    int E = in_sizes[1] / 2;
    int nb = (N + 1023) / 1024;

    zero_detect_kernel<<<(N + 255) / 256, 256>>>(ei, N);
    int repack_threads = 2 * (NDEG * 32 * 32) + 2 * (NDEG * 8 * 64);
    repack_kernel<<<(repack_threads + 255) / 256, 256>>>(W1, Wr1, W2, Wr2);
    count_kernel<<<(E + 255) / 256, 256>>>(ei, E, N);
    scan1_kernel<<<nb, 1024>>>(N);
    scan2_kernel<<<1, 256>>>(nb);
    scan3_kernel<<<(N + 255) / 256, 256>>>(N);
    fill_kernel<<<(E + 255) / 256, 256>>>(ei, E, N);
    layer1_kernel<<<(N + 31) / 32, 256>>>(x, b1, N);
    layer2_kernel<<<(N + 31) / 32, 256>>>(b2, (float*)d_out, N);
}

// round 13
// speedup vs baseline: 1.1208x; 1.1208x over previous
#include <cuda_runtime.h>
#include <cuda_bf16.h>
#include <cstdint>

#define F_IN   128
#define F_HID  32
#define F_OUT  64
#define NDEG   11
#define MAXDEG 10
#define MAXN   100000
#define MAXE   1600000

// ---- scratch (__device__ globals; no allocation allowed) ----
__device__ int    g_is64;
__device__ int    g_deg[MAXN];
__device__ int    g_rowstart[MAXN];
__device__ int    g_cursor[MAXN];
__device__ int    g_csrc[MAXE];
__device__ int    g_bsum[256];
__device__ float  g_h1[MAXN * F_IN];     // layer-1 neighbor sums (51MB)
__device__ float  g_h2[MAXN * F_HID];    // relu(layer-1 out)
__device__ float  g_agg2[MAXN * F_HID];  // layer-2 neighbor sums
// packed weights: [d][k/4][o] as float4 over the 4 k-components
__device__ float4 g_W1p [NDEG * 32 * 32];
__device__ float4 g_Wr1p[NDEG * 32 * 32];
__device__ float4 g_W2p [NDEG * 8  * 64];
__device__ float4 g_Wr2p[NDEG * 8  * 64];

// edge_index may be int32 (jax default) or int64 (x64 enabled). Branch on flag.
__device__ __forceinline__ int edge_at(const void* ei, long long pos) {
    if (g_is64) return (int)((const long long*)ei)[pos];
    return ((const int*)ei)[pos];
}

// ---- zero + dtype sniff fused ----
__global__ void zero_detect_kernel(const void* ei, int N) {
    int i = blockIdx.x * blockDim.x + threadIdx.x;
    if (i < N) { g_deg[i] = 0; g_cursor[i] = 0; }
    if (blockIdx.x == 0 && threadIdx.x == 0) {
        const int* p = (const int*)ei;
        int zeros = 0;
#pragma unroll
        for (int j = 0; j < 32; j++)
            if (p[2 * j + 1] == 0) zeros++;
        g_is64 = (zeros >= 30) ? 1 : 0;
    }
}

// ---- repack weights into k-grouped float4 layout (tiny) ----
__global__ void repack_kernel(const float* __restrict__ W1, const float* __restrict__ Wr1,
                              const float* __restrict__ W2, const float* __restrict__ Wr2) {
    const int n1 = NDEG * 32 * 32;  // 11264
    const int n2 = NDEG * 8 * 64;   // 5632
    int t = blockIdx.x * blockDim.x + threadIdx.x;
    if (t < 2 * n1) {
        int u = (t < n1) ? t : t - n1;
        const float* src = (t < n1) ? W1 : Wr1;
        float4* dst = (t < n1) ? g_W1p : g_Wr1p;
        int d = u / 1024, r = u % 1024, g = r / 32, o = r % 32;
        int b = d * F_IN * F_HID + (4 * g) * F_HID + o;
        dst[u] = make_float4(src[b], src[b + F_HID], src[b + 2 * F_HID], src[b + 3 * F_HID]);
    } else if (t < 2 * n1 + 2 * n2) {
        int v = t - 2 * n1;
        int u = (v < n2) ? v : v - n2;
        const float* src = (v < n2) ? W2 : Wr2;
        float4* dst = (v < n2) ? g_W2p : g_Wr2p;
        int d = u / 512, r = u % 512, g = r / 64, o = r % 64;
        int b = d * F_HID * F_OUT + (4 * g) * F_OUT + o;
        dst[u] = make_float4(src[b], src[b + F_OUT], src[b + 2 * F_OUT], src[b + 3 * F_OUT]);
    }
}

// ---- degree count ----
__global__ void count_kernel(const void* __restrict__ ei, int E, int N) {
    int e = blockIdx.x * blockDim.x + threadIdx.x;
    if (e >= E) return;
    int dst = edge_at(ei, (long long)E + e);
    if ((unsigned)dst >= (unsigned)N) return;
    atomicAdd(&g_deg[dst], 1);
}

// ---- exclusive scan of g_deg -> g_rowstart (3 stages) ----
__global__ void scan1_kernel(int N) {
    __shared__ int s[1024];
    int i = blockIdx.x * 1024 + threadIdx.x;
    int v = (i < N) ? g_deg[i] : 0;
    s[threadIdx.x] = v;
    __syncthreads();
    for (int off = 1; off < 1024; off <<= 1) {
        int t = (threadIdx.x >= off) ? s[threadIdx.x - off] : 0;
        __syncthreads();
        s[threadIdx.x] += t;
        __syncthreads();
    }
    if (i < N) g_rowstart[i] = s[threadIdx.x] - v;
    if (threadIdx.x == 1023) g_bsum[blockIdx.x] = s[1023];
}

__global__ void scan2_kernel(int nb) {
    __shared__ int s[256];
    int v = (threadIdx.x < nb) ? g_bsum[threadIdx.x] : 0;
    s[threadIdx.x] = v;
    __syncthreads();
    for (int off = 1; off < 256; off <<= 1) {
        int t = (threadIdx.x >= off) ? s[threadIdx.x - off] : 0;
        __syncthreads();
        s[threadIdx.x] += t;
        __syncthreads();
    }
    if (threadIdx.x < nb) g_bsum[threadIdx.x] = s[threadIdx.x] - v;
}

__global__ void scan3_kernel(int N) {
    int i = blockIdx.x * blockDim.x + threadIdx.x;
    if (i < N) g_rowstart[i] += g_bsum[i >> 10];
}

// ---- CSR fill ----
__global__ void fill_kernel(const void* __restrict__ ei, int E, int N) {
    int e = blockIdx.x * blockDim.x + threadIdx.x;
    if (e >= E) return;
    int src = edge_at(ei, e);
    int dst = edge_at(ei, (long long)E + e);
    if ((unsigned)dst >= (unsigned)N || (unsigned)src >= (unsigned)N) return;
    int pos = atomicAdd(&g_cursor[dst], 1);
    g_csrc[g_rowstart[dst] + pos] = src;
}

// ---- A1: layer-1 gather. warp per node, lane = float4 chunk, MLP=8 ----
__global__ void agg1_kernel(const float* __restrict__ x, int N) {
    int warp = threadIdx.x >> 5, lane = threadIdx.x & 31;
    int n = blockIdx.x * 8 + warp;
    if (n >= N) return;
    int d = g_deg[n];
    int start = g_rowstart[n];
    const float4* xv = (const float4*)x;
    float4 hacc = make_float4(0.f, 0.f, 0.f, 0.f);
    int k = 0;
    for (; k + 8 <= d; k += 8) {
        int s0 = g_csrc[start + k + 0];
        int s1 = g_csrc[start + k + 1];
        int s2 = g_csrc[start + k + 2];
        int s3 = g_csrc[start + k + 3];
        int s4 = g_csrc[start + k + 4];
        int s5 = g_csrc[start + k + 5];
        int s6 = g_csrc[start + k + 6];
        int s7 = g_csrc[start + k + 7];
        float4 v0 = xv[(size_t)s0 * 32 + lane];
        float4 v1 = xv[(size_t)s1 * 32 + lane];
        float4 v2 = xv[(size_t)s2 * 32 + lane];
        float4 v3 = xv[(size_t)s3 * 32 + lane];
        float4 v4 = xv[(size_t)s4 * 32 + lane];
        float4 v5 = xv[(size_t)s5 * 32 + lane];
        float4 v6 = xv[(size_t)s6 * 32 + lane];
        float4 v7 = xv[(size_t)s7 * 32 + lane];
        hacc.x += ((v0.x + v1.x) + (v2.x + v3.x)) + ((v4.x + v5.x) + (v6.x + v7.x));
        hacc.y += ((v0.y + v1.y) + (v2.y + v3.y)) + ((v4.y + v5.y) + (v6.y + v7.y));
        hacc.z += ((v0.z + v1.z) + (v2.z + v3.z)) + ((v4.z + v5.z) + (v6.z + v7.z));
        hacc.w += ((v0.w + v1.w) + (v2.w + v3.w)) + ((v4.w + v5.w) + (v6.w + v7.w));
    }
    for (; k < d; k++) {
        int s = g_csrc[start + k];
        float4 v = xv[(size_t)s * 32 + lane];
        hacc.x += v.x; hacc.y += v.y; hacc.z += v.z; hacc.w += v.w;
    }
    ((float4*)g_h1)[(size_t)n * 32 + lane] = hacc;
}

// ---- B1: layer-1 GEMV. warp per 8 nodes; weights 8x amortized; no smem ----
__global__ void gemv1_kernel(const float* __restrict__ x, const float* __restrict__ b1, int N) {
    int warp = threadIdx.x >> 5, lane = threadIdx.x & 31;
    int base = (blockIdx.x * 8 + warp) * 8;
    if (base >= N) return;
    const float4* h1v = (const float4*)g_h1;
    const float4* xv  = (const float4*)x;
    int dcs[8];
#pragma unroll
    for (int i = 0; i < 8; i++) {
        int n = base + i;
        dcs[i] = (n < N) ? min(g_deg[n], MAXDEG) : -1;
    }
    bool allsame = true;
#pragma unroll
    for (int i = 1; i < 8; i++) allsame = allsame && (dcs[i] == dcs[0]);

    if (allsame) {
        int dc = dcs[0];
        float bias = b1[dc * F_HID + lane];
        float acc[8];
#pragma unroll
        for (int i = 0; i < 8; i++) acc[i] = bias;
        const float4* w1 = &g_W1p [dc * 1024 + lane];
        const float4* wr = &g_Wr1p[dc * 1024 + lane];
        for (int g = 0; g < 32; g++) {
            float4 a = w1[g * 32];
            float4 b = wr[g * 32];
#pragma unroll
            for (int i = 0; i < 8; i++) {
                float4 hh = h1v[(size_t)(base + i) * 32 + g];  // uniform broadcast
                float4 xx = xv [(size_t)(base + i) * 32 + g];
                acc[i] += hh.x * a.x + hh.y * a.y + hh.z * a.z + hh.w * a.w
                        + xx.x * b.x + xx.y * b.y + xx.z * b.z + xx.w * b.w;
            }
        }
#pragma unroll
        for (int i = 0; i < 8; i++)
            g_h2[(size_t)(base + i) * F_HID + lane] = fmaxf(acc[i], 0.f);
    } else {
#pragma unroll 1
        for (int i = 0; i < 8; i++) {
            if (dcs[i] < 0) continue;
            int dc = dcs[i];
            float acc = b1[dc * F_HID + lane];
            const float4* w1 = &g_W1p [dc * 1024 + lane];
            const float4* wr = &g_Wr1p[dc * 1024 + lane];
            for (int g = 0; g < 32; g++) {
                float4 hh = h1v[(size_t)(base + i) * 32 + g];
                float4 xx = xv [(size_t)(base + i) * 32 + g];
                float4 a = w1[g * 32];
                float4 b = wr[g * 32];
                acc += hh.x * a.x + hh.y * a.y + hh.z * a.z + hh.w * a.w
                     + xx.x * b.x + xx.y * b.y + xx.z * b.z + xx.w * b.w;
            }
            g_h2[(size_t)(base + i) * F_HID + lane] = fmaxf(acc, 0.f);
        }
    }
}

// ---- A2: layer-2 gather. warp per node, lane = float chunk, MLP=8 ----
__global__ void agg2_kernel(int N) {
    int warp = threadIdx.x >> 5, lane = threadIdx.x & 31;
    int n = blockIdx.x * 8 + warp;
    if (n >= N) return;
    int d = g_deg[n];
    int start = g_rowstart[n];
    float hacc = 0.f;
    int k = 0;
    for (; k + 8 <= d; k += 8) {
        int s0 = g_csrc[start + k + 0];
        int s1 = g_csrc[start + k + 1];
        int s2 = g_csrc[start + k + 2];
        int s3 = g_csrc[start + k + 3];
        int s4 = g_csrc[start + k + 4];
        int s5 = g_csrc[start + k + 5];
        int s6 = g_csrc[start + k + 6];
        int s7 = g_csrc[start + k + 7];
        float v0 = g_h2[(size_t)s0 * F_HID + lane];
        float v1 = g_h2[(size_t)s1 * F_HID + lane];
        float v2 = g_h2[(size_t)s2 * F_HID + lane];
        float v3 = g_h2[(size_t)s3 * F_HID + lane];
        float v4 = g_h2[(size_t)s4 * F_HID + lane];
        float v5 = g_h2[(size_t)s5 * F_HID + lane];
        float v6 = g_h2[(size_t)s6 * F_HID + lane];
        float v7 = g_h2[(size_t)s7 * F_HID + lane];
        hacc += ((v0 + v1) + (v2 + v3)) + ((v4 + v5) + (v6 + v7));
    }
    for (; k < d; k++) {
        int s = g_csrc[start + k];
        hacc += g_h2[(size_t)s * F_HID + lane];
    }
    g_agg2[(size_t)n * F_HID + lane] = hacc;
}

// ---- B2: layer-2 GEMV. warp per 8 nodes; lane owns outputs {lane, lane+32} ----
__global__ void gemv2_kernel(const float* __restrict__ b2, float* __restrict__ out, int N) {
    int warp = threadIdx.x >> 5, lane = threadIdx.x & 31;
    int base = (blockIdx.x * 8 + warp) * 8;
    if (base >= N) return;
    const float4* aggv = (const float4*)g_agg2;
    const float4* h2v  = (const float4*)g_h2;
    int dcs[8];
#pragma unroll
    for (int i = 0; i < 8; i++) {
        int n = base + i;
        dcs[i] = (n < N) ? min(g_deg[n], MAXDEG) : -1;
    }
    bool allsame = true;
#pragma unroll
    for (int i = 1; i < 8; i++) allsame = allsame && (dcs[i] == dcs[0]);

    if (allsame) {
        int dc = dcs[0];
        float blo = b2[dc * F_OUT + lane];
        float bhi = b2[dc * F_OUT + 32 + lane];
        float acc0[8], acc1[8];
#pragma unroll
        for (int i = 0; i < 8; i++) { acc0[i] = blo; acc1[i] = bhi; }
        const float4* w2  = &g_W2p [dc * 512];
        const float4* wr2 = &g_Wr2p[dc * 512];
#pragma unroll
        for (int g = 0; g < 8; g++) {
            float4 a0 = w2 [g * 64 + lane];
            float4 a1 = w2 [g * 64 + 32 + lane];
            float4 r0 = wr2[g * 64 + lane];
            float4 r1 = wr2[g * 64 + 32 + lane];
#pragma unroll
            for (int i = 0; i < 8; i++) {
                float4 hh = aggv[(size_t)(base + i) * 8 + g];  // uniform broadcast
                float4 xx = h2v [(size_t)(base + i) * 8 + g];
                acc0[i] += hh.x * a0.x + hh.y * a0.y + hh.z * a0.z + hh.w * a0.w
                         + xx.x * r0.x + xx.y * r0.y + xx.z * r0.z + xx.w * r0.w;
                acc1[i] += hh.x * a1.x + hh.y * a1.y + hh.z * a1.z + hh.w * a1.w
                         + xx.x * r1.x + xx.y * r1.y + xx.z * r1.z + xx.w * r1.w;
            }
        }
#pragma unroll
        for (int i = 0; i < 8; i++) {
            out[(size_t)(base + i) * F_OUT + lane]      = acc0[i];
            out[(size_t)(base + i) * F_OUT + 32 + lane] = acc1[i];
        }
    } else {
#pragma unroll 1
        for (int i = 0; i < 8; i++) {
            if (dcs[i] < 0) continue;
            int dc = dcs[i];
            float acc0 = b2[dc * F_OUT + lane];
            float acc1 = b2[dc * F_OUT + 32 + lane];
            const float4* w2  = &g_W2p [dc * 512];
            const float4* wr2 = &g_Wr2p[dc * 512];
#pragma unroll
            for (int g = 0; g < 8; g++) {
                float4 hh = aggv[(size_t)(base + i) * 8 + g];
                float4 xx = h2v [(size_t)(base + i) * 8 + g];
                float4 a0 = w2 [g * 64 + lane];
                float4 a1 = w2 [g * 64 + 32 + lane];
                float4 r0 = wr2[g * 64 + lane];
                float4 r1 = wr2[g * 64 + 32 + lane];
                acc0 += hh.x * a0.x + hh.y * a0.y + hh.z * a0.z + hh.w * a0.w
                      + xx.x * r0.x + xx.y * r0.y + xx.z * r0.z + xx.w * r0.w;
                acc1 += hh.x * a1.x + hh.y * a1.y + hh.z * a1.z + hh.w * a1.w
                      + xx.x * r1.x + xx.y * r1.y + xx.z * r1.z + xx.w * r1.w;
            }
            out[(size_t)(base + i) * F_OUT + lane]      = acc0;
            out[(size_t)(base + i) * F_OUT + 32 + lane] = acc1;
        }
    }
}

extern "C" void kernel_launch(void* const* d_in, const int* in_sizes, int n_in,
                              void* d_out, int out_size) {
    const float* x   = (const float*)d_in[0];
    const void*  ei  = d_in[1];
    const float* W1  = (const float*)d_in[2];
    const float* b1  = (const float*)d_in[3];
    const float* Wr1 = (const float*)d_in[4];
    const float* W2  = (const float*)d_in[5];
    const float* b2  = (const float*)d_in[6];
    const float* Wr2 = (const float*)d_in[7];

    int N = in_sizes[0] / F_IN;
    int E = in_sizes[1] / 2;
    int nb = (N + 1023) / 1024;

    zero_detect_kernel<<<(N + 255) / 256, 256>>>(ei, N);
    int repack_threads = 2 * (NDEG * 32 * 32) + 2 * (NDEG * 8 * 64);
    repack_kernel<<<(repack_threads + 255) / 256, 256>>>(W1, Wr1, W2, Wr2);
    count_kernel<<<(E + 255) / 256, 256>>>(ei, E, N);
    scan1_kernel<<<nb, 1024>>>(N);
    scan2_kernel<<<1, 256>>>(nb);
    scan3_kernel<<<(N + 255) / 256, 256>>>(N);
    fill_kernel<<<(E + 255) / 256, 256>>>(ei, E, N);

    agg1_kernel <<<(N + 7) / 8, 256>>>(x, N);
    gemv1_kernel<<<(N + 63) / 64, 256>>>(x, b1, N);
    agg2_kernel <<<(N + 7) / 8, 256>>>(N);
    gemv2_kernel<<<(N + 63) / 64, 256>>>(b2, (float*)d_out, N);
}

// round 15
// speedup vs baseline: 1.5042x; 1.3421x over previous
#include <cuda_runtime.h>
#include <cuda_bf16.h>
#include <cstdint>

#define F_IN   128
#define F_HID  32
#define F_OUT  64
#define NDEG   11
#define MAXDEG 10
#define MAXN   100000
#define MAXE   1600000

// ---- scratch (__device__ globals; no allocation allowed) ----
__device__ int    g_is64;
__device__ int    g_deg[MAXN];
__device__ int    g_rowstart[MAXN];
__device__ int    g_cursor[MAXN];
__device__ int    g_csrc[MAXE];
__device__ int    g_bsum[256];
__device__ float  g_h2[MAXN * F_HID];    // relu(layer-1 out)
// packed weights: [d][k/4][o] as float4 over the 4 k-components
__device__ float4 g_W1p [NDEG * 32 * 32];
__device__ float4 g_Wr1p[NDEG * 32 * 32];
__device__ float4 g_W2p [NDEG * 8  * 64];
__device__ float4 g_Wr2p[NDEG * 8  * 64];

// edge_index may be int32 (jax default) or int64 (x64 enabled). Branch on flag.
__device__ __forceinline__ int edge_at(const void* ei, long long pos) {
    if (g_is64) return (int)((const long long*)ei)[pos];
    return ((const int*)ei)[pos];
}

// ---- zero + dtype sniff fused ----
__global__ void zero_detect_kernel(const void* ei, int N) {
    int i = blockIdx.x * blockDim.x + threadIdx.x;
    if (i < N) { g_deg[i] = 0; g_cursor[i] = 0; }
    if (blockIdx.x == 0 && threadIdx.x == 0) {
        const int* p = (const int*)ei;
        int zeros = 0;
#pragma unroll
        for (int j = 0; j < 32; j++)
            if (p[2 * j + 1] == 0) zeros++;
        g_is64 = (zeros >= 30) ? 1 : 0;
    }
}

// ---- repack weights into k-grouped float4 layout (tiny) ----
__global__ void repack_kernel(const float* __restrict__ W1, const float* __restrict__ Wr1,
                              const float* __restrict__ W2, const float* __restrict__ Wr2) {
    const int n1 = NDEG * 32 * 32;  // 11264
    const int n2 = NDEG * 8 * 64;   // 5632
    int t = blockIdx.x * blockDim.x + threadIdx.x;
    if (t < 2 * n1) {
        int u = (t < n1) ? t : t - n1;
        const float* src = (t < n1) ? W1 : Wr1;
        float4* dst = (t < n1) ? g_W1p : g_Wr1p;
        int d = u / 1024, r = u % 1024, g = r / 32, o = r % 32;
        int b = d * F_IN * F_HID + (4 * g) * F_HID + o;
        dst[u] = make_float4(src[b], src[b + F_HID], src[b + 2 * F_HID], src[b + 3 * F_HID]);
    } else if (t < 2 * n1 + 2 * n2) {
        int v = t - 2 * n1;
        int u = (v < n2) ? v : v - n2;
        const float* src = (v < n2) ? W2 : Wr2;
        float4* dst = (v < n2) ? g_W2p : g_Wr2p;
        int d = u / 512, r = u % 512, g = r / 64, o = r % 64;
        int b = d * F_HID * F_OUT + (4 * g) * F_OUT + o;
        dst[u] = make_float4(src[b], src[b + F_OUT], src[b + 2 * F_OUT], src[b + 3 * F_OUT]);
    }
}

// ---- degree count ----
__global__ void count_kernel(const void* __restrict__ ei, int E, int N) {
    int e = blockIdx.x * blockDim.x + threadIdx.x;
    if (e >= E) return;
    int dst = edge_at(ei, (long long)E + e);
    if ((unsigned)dst >= (unsigned)N) return;
    atomicAdd(&g_deg[dst], 1);
}

// ---- exclusive scan of g_deg -> g_rowstart (3 stages) ----
__global__ void scan1_kernel(int N) {
    __shared__ int s[1024];
    int i = blockIdx.x * 1024 + threadIdx.x;
    int v = (i < N) ? g_deg[i] : 0;
    s[threadIdx.x] = v;
    __syncthreads();
    for (int off = 1; off < 1024; off <<= 1) {
        int t = (threadIdx.x >= off) ? s[threadIdx.x - off] : 0;
        __syncthreads();
        s[threadIdx.x] += t;
        __syncthreads();
    }
    if (i < N) g_rowstart[i] = s[threadIdx.x] - v;
    if (threadIdx.x == 1023) g_bsum[blockIdx.x] = s[1023];
}

__global__ void scan2_kernel(int nb) {
    __shared__ int s[256];
    int v = (threadIdx.x < nb) ? g_bsum[threadIdx.x] : 0;
    s[threadIdx.x] = v;
    __syncthreads();
    for (int off = 1; off < 256; off <<= 1) {
        int t = (threadIdx.x >= off) ? s[threadIdx.x - off] : 0;
        __syncthreads();
        s[threadIdx.x] += t;
        __syncthreads();
    }
    if (threadIdx.x < nb) g_bsum[threadIdx.x] = s[threadIdx.x] - v;
}

__global__ void scan3_kernel(int N) {
    int i = blockIdx.x * blockDim.x + threadIdx.x;
    if (i < N) g_rowstart[i] += g_bsum[i >> 10];
}

// ---- CSR fill ----
__global__ void fill_kernel(const void* __restrict__ ei, int E, int N) {
    int e = blockIdx.x * blockDim.x + threadIdx.x;
    if (e >= E) return;
    int src = edge_at(ei, e);
    int dst = edge_at(ei, (long long)E + e);
    if ((unsigned)dst >= (unsigned)N || (unsigned)src >= (unsigned)N) return;
    int pos = atomicAdd(&g_cursor[dst], 1);
    g_csrc[g_rowstart[dst] + pos] = src;
}

// ---- fused layer-1: 8 warps = 8 nodes per block.
//  phase 1: warp-per-node gather (full parallelism)
//  phase 2: warp w owns k-groups [4w,4w+4); computes partials for ALL 8 nodes
//           with dc=10 weights (8x weight-traffic reduction)
//  phase 3: warp-per-node partial reduction; dc!=10 nodes recomputed solo.
__global__ void layer1_kernel(const float* __restrict__ x, const float* __restrict__ b1, int N) {
    __shared__ float sh_act[8][256];      // per node: h[128] | x[128]
    __shared__ float sh_part[8][8][32];   // [warp][node][out]
    __shared__ int   sh_dc[8];
    int warp = threadIdx.x >> 5, lane = threadIdx.x & 31;
    int base = blockIdx.x * 8;
    int n = base + warp;
    const float4* xv = (const float4*)x;

    // phase 1: gather
    int dc = -1;
    if (n < N) {
        int d = g_deg[n];
        int start = g_rowstart[n];
        float4 hacc = make_float4(0.f, 0.f, 0.f, 0.f);
        int k = 0;
        for (; k + 8 <= d; k += 8) {
            int s0 = g_csrc[start + k + 0];
            int s1 = g_csrc[start + k + 1];
            int s2 = g_csrc[start + k + 2];
            int s3 = g_csrc[start + k + 3];
            int s4 = g_csrc[start + k + 4];
            int s5 = g_csrc[start + k + 5];
            int s6 = g_csrc[start + k + 6];
            int s7 = g_csrc[start + k + 7];
            float4 v0 = xv[(size_t)s0 * 32 + lane];
            float4 v1 = xv[(size_t)s1 * 32 + lane];
            float4 v2 = xv[(size_t)s2 * 32 + lane];
            float4 v3 = xv[(size_t)s3 * 32 + lane];
            float4 v4 = xv[(size_t)s4 * 32 + lane];
            float4 v5 = xv[(size_t)s5 * 32 + lane];
            float4 v6 = xv[(size_t)s6 * 32 + lane];
            float4 v7 = xv[(size_t)s7 * 32 + lane];
            hacc.x += ((v0.x + v1.x) + (v2.x + v3.x)) + ((v4.x + v5.x) + (v6.x + v7.x));
            hacc.y += ((v0.y + v1.y) + (v2.y + v3.y)) + ((v4.y + v5.y) + (v6.y + v7.y));
            hacc.z += ((v0.z + v1.z) + (v2.z + v3.z)) + ((v4.z + v5.z) + (v6.z + v7.z));
            hacc.w += ((v0.w + v1.w) + (v2.w + v3.w)) + ((v4.w + v5.w) + (v6.w + v7.w));
        }
        for (; k < d; k++) {
            int s = g_csrc[start + k];
            float4 v = xv[(size_t)s * 32 + lane];
            hacc.x += v.x; hacc.y += v.y; hacc.z += v.z; hacc.w += v.w;
        }
        ((float4*)&sh_act[warp][0])[lane]   = hacc;
        ((float4*)&sh_act[warp][128])[lane] = xv[(size_t)n * 32 + lane];
        dc = min(d, MAXDEG);
    } else {
        ((float4*)&sh_act[warp][0])[lane]   = make_float4(0.f, 0.f, 0.f, 0.f);
        ((float4*)&sh_act[warp][128])[lane] = make_float4(0.f, 0.f, 0.f, 0.f);
    }
    if (lane == 0) sh_dc[warp] = dc;
    __syncthreads();

    // phase 2: k-split partials with dc=10 weights (speculative for all 8 nodes)
    {
        float part[8];
#pragma unroll
        for (int i = 0; i < 8; i++) part[i] = 0.f;
        const float4* w1 = &g_W1p [MAXDEG * 1024 + lane];
        const float4* wr = &g_Wr1p[MAXDEG * 1024 + lane];
#pragma unroll
        for (int gg = 0; gg < 4; gg++) {
            int g = warp * 4 + gg;
            float4 a = w1[g * 32];
            float4 b = wr[g * 32];
#pragma unroll
            for (int i = 0; i < 8; i++) {
                float4 hh = *(const float4*)&sh_act[i][4 * g];
                float4 xx = *(const float4*)&sh_act[i][128 + 4 * g];
                part[i] += hh.x * a.x + hh.y * a.y + hh.z * a.z + hh.w * a.w
                         + xx.x * b.x + xx.y * b.y + xx.z * b.z + xx.w * b.w;
            }
        }
#pragma unroll
        for (int i = 0; i < 8; i++) sh_part[warp][i][lane] = part[i];
    }
    __syncthreads();

    // phase 2b: rare non-clamped nodes: own warp recomputes fully
    if (dc >= 0 && dc != MAXDEG) {
        float acc = b1[dc * F_HID + lane];
        const float4* w1 = &g_W1p [dc * 1024 + lane];
        const float4* wr = &g_Wr1p[dc * 1024 + lane];
#pragma unroll 8
        for (int g = 0; g < 32; g++) {
            float4 hh = *(const float4*)&sh_act[warp][4 * g];
            float4 xx = *(const float4*)&sh_act[warp][128 + 4 * g];
            float4 a = w1[g * 32];
            float4 b = wr[g * 32];
            acc += hh.x * a.x + hh.y * a.y + hh.z * a.z + hh.w * a.w
                 + xx.x * b.x + xx.y * b.y + xx.z * b.z + xx.w * b.w;
        }
        g_h2[(size_t)n * F_HID + lane] = fmaxf(acc, 0.f);
    }

    // phase 3: reduce partials for dc==10 nodes
    if (dc == MAXDEG) {
        float acc = b1[MAXDEG * F_HID + lane];
#pragma unroll
        for (int w = 0; w < 8; w++) acc += sh_part[w][warp][lane];
        g_h2[(size_t)n * F_HID + lane] = fmaxf(acc, 0.f);
    }
}

// ---- fused layer-2: same structure; warp w owns k-group g=w ----
__global__ void layer2_kernel(const float* __restrict__ b2, float* __restrict__ out, int N) {
    __shared__ float sh_act[8][64];        // per node: agg[32] | h2[32]
    __shared__ float sh_p0[8][8][32];      // [warp][node][out lo]
    __shared__ float sh_p1[8][8][32];      // [warp][node][out hi]
    __shared__ int   sh_dc[8];
    int warp = threadIdx.x >> 5, lane = threadIdx.x & 31;
    int base = blockIdx.x * 8;
    int n = base + warp;

    // phase 1: gather
    int dc = -1;
    if (n < N) {
        int d = g_deg[n];
        int start = g_rowstart[n];
        float hacc = 0.f;
        int k = 0;
        for (; k + 8 <= d; k += 8) {
            int s0 = g_csrc[start + k + 0];
            int s1 = g_csrc[start + k + 1];
            int s2 = g_csrc[start + k + 2];
            int s3 = g_csrc[start + k + 3];
            int s4 = g_csrc[start + k + 4];
            int s5 = g_csrc[start + k + 5];
            int s6 = g_csrc[start + k + 6];
            int s7 = g_csrc[start + k + 7];
            float v0 = g_h2[(size_t)s0 * F_HID + lane];
            float v1 = g_h2[(size_t)s1 * F_HID + lane];
            float v2 = g_h2[(size_t)s2 * F_HID + lane];
            float v3 = g_h2[(size_t)s3 * F_HID + lane];
            float v4 = g_h2[(size_t)s4 * F_HID + lane];
            float v5 = g_h2[(size_t)s5 * F_HID + lane];
            float v6 = g_h2[(size_t)s6 * F_HID + lane];
            float v7 = g_h2[(size_t)s7 * F_HID + lane];
            hacc += ((v0 + v1) + (v2 + v3)) + ((v4 + v5) + (v6 + v7));
        }
        for (; k < d; k++) {
            int s = g_csrc[start + k];
            hacc += g_h2[(size_t)s * F_HID + lane];
        }
        sh_act[warp][lane]      = hacc;
        sh_act[warp][32 + lane] = g_h2[(size_t)n * F_HID + lane];
        dc = min(d, MAXDEG);
    } else {
        sh_act[warp][lane]      = 0.f;
        sh_act[warp][32 + lane] = 0.f;
    }
    if (lane == 0) sh_dc[warp] = dc;
    __syncthreads();

    // phase 2: k-split partials with dc=10 weights; warp handles g = warp
    {
        float p0[8], p1[8];
#pragma unroll
        for (int i = 0; i < 8; i++) { p0[i] = 0.f; p1[i] = 0.f; }
        int g = warp;
        const float4* w2  = &g_W2p [MAXDEG * 512];
        const float4* wr2 = &g_Wr2p[MAXDEG * 512];
        float4 a0 = w2 [g * 64 + lane];
        float4 a1 = w2 [g * 64 + 32 + lane];
        float4 r0 = wr2[g * 64 + lane];
        float4 r1 = wr2[g * 64 + 32 + lane];
#pragma unroll
        for (int i = 0; i < 8; i++) {
            float4 hh = *(const float4*)&sh_act[i][4 * g];
            float4 xx = *(const float4*)&sh_act[i][32 + 4 * g];
            p0[i] = hh.x * a0.x + hh.y * a0.y + hh.z * a0.z + hh.w * a0.w
                  + xx.x * r0.x + xx.y * r0.y + xx.z * r0.z + xx.w * r0.w;
            p1[i] = hh.x * a1.x + hh.y * a1.y + hh.z * a1.z + hh.w * a1.w
                  + xx.x * r1.x + xx.y * r1.y + xx.z * r1.z + xx.w * r1.w;
        }
#pragma unroll
        for (int i = 0; i < 8; i++) { sh_p0[warp][i][lane] = p0[i]; sh_p1[warp][i][lane] = p1[i]; }
    }
    __syncthreads();

    // phase 2b: rare non-clamped nodes
    if (dc >= 0 && dc != MAXDEG) {
        float acc0 = b2[dc * F_OUT + lane];
        float acc1 = b2[dc * F_OUT + 32 + lane];
        const float4* w2  = &g_W2p [dc * 512];
        const float4* wr2 = &g_Wr2p[dc * 512];
#pragma unroll
        for (int g = 0; g < 8; g++) {
            float4 hh = *(const float4*)&sh_act[warp][4 * g];
            float4 xx = *(const float4*)&sh_act[warp][32 + 4 * g];
            float4 a0 = w2 [g * 64 + lane];
            float4 a1 = w2 [g * 64 + 32 + lane];
            float4 r0 = wr2[g * 64 + lane];
            float4 r1 = wr2[g * 64 + 32 + lane];
            acc0 += hh.x * a0.x + hh.y * a0.y + hh.z * a0.z + hh.w * a0.w
                  + xx.x * r0.x + xx.y * r0.y + xx.z * r0.z + xx.w * r0.w;
            acc1 += hh.x * a1.x + hh.y * a1.y + hh.z * a1.z + hh.w * a1.w
                  + xx.x * r1.x + xx.y * r1.y + xx.z * r1.z + xx.w * r1.w;
        }
        out[(size_t)n * F_OUT + lane]      = acc0;
        out[(size_t)n * F_OUT + 32 + lane] = acc1;
    }

    // phase 3: reduce
    if (dc == MAXDEG) {
        float acc0 = b2[MAXDEG * F_OUT + lane];
        float acc1 = b2[MAXDEG * F_OUT + 32 + lane];
#pragma unroll
        for (int w = 0; w < 8; w++) { acc0 += sh_p0[w][warp][lane]; acc1 += sh_p1[w][warp][lane]; }
        out[(size_t)n * F_OUT + lane]      = acc0;
        out[(size_t)n * F_OUT + 32 + lane] = acc1;
    }
}

extern "C" void kernel_launch(void* const* d_in, const int* in_sizes, int n_in,
                              void* d_out, int out_size) {
    const float* x   = (const float*)d_in[0];
    const void*  ei  = d_in[1];
    const float* W1  = (const float*)d_in[2];
    const float* b1  = (const float*)d_in[3];
    const float* Wr1 = (const float*)d_in[4];
    const float* W2  = (const float*)d_in[5];
    const float* b2  = (const float*)d_in[6];
    const float* Wr2 = (const float*)d_in[7];

    int N = in_sizes[0] / F_IN;
    int E = in_sizes[1] / 2;
    int nb = (N + 1023) / 1024;

    zero_detect_kernel<<<(N + 255) / 256, 256>>>(ei, N);
    int repack_threads = 2 * (NDEG * 32 * 32) + 2 * (NDEG * 8 * 64);
    repack_kernel<<<(repack_threads + 255) / 256, 256>>>(W1, Wr1, W2, Wr2);
    count_kernel<<<(E + 255) / 256, 256>>>(ei, E, N);
    scan1_kernel<<<nb, 1024>>>(N);
    scan2_kernel<<<1, 256>>>(nb);
    scan3_kernel<<<(N + 255) / 256, 256>>>(N);
    fill_kernel<<<(E + 255) / 256, 256>>>(ei, E, N);

    layer1_kernel<<<(N + 7) / 8, 256>>>(x, b1, N);
    layer2_kernel<<<(N + 7) / 8, 256>>>(b2, (float*)d_out, N);
}

// round 16
// speedup vs baseline: 1.6496x; 1.0966x over previous
#include <cuda_runtime.h>
#include <cuda_bf16.h>
#include <cstdint>

#define F_IN   128
#define F_HID  32
#define F_OUT  64
#define NDEG   11
#define MAXDEG 10
#define MAXN   100000
#define MAXE   1600000

// ---- scratch (__device__ globals; no allocation allowed) ----
__device__ int    g_is64;
__device__ int    g_deg[MAXN];
__device__ int    g_rowstart[MAXN];
__device__ int    g_cursor[MAXN];
__device__ int    g_csrc[MAXE];
__device__ int    g_bsum[256];
__device__ float  g_p1[MAXN * F_HID];    // W1[10] . x_n   (projected neighbors)
__device__ float  g_r1[MAXN * F_HID];    // Wr1[10] . x_n  (projected root)
__device__ float  g_h2[MAXN * F_HID];    // relu(layer-1 out)
// packed weights: [d][k/4][o] as float4 over the 4 k-components
__device__ float4 g_W1p [NDEG * 32 * 32];
__device__ float4 g_Wr1p[NDEG * 32 * 32];
__device__ float4 g_W2p [NDEG * 8  * 64];
__device__ float4 g_Wr2p[NDEG * 8  * 64];

// edge_index may be int32 (jax default) or int64 (x64 enabled). Branch on flag.
__device__ __forceinline__ int edge_at(const void* ei, long long pos) {
    if (g_is64) return (int)((const long long*)ei)[pos];
    return ((const int*)ei)[pos];
}

// ---- zero + dtype sniff fused ----
__global__ void zero_detect_kernel(const void* ei, int N) {
    int i = blockIdx.x * blockDim.x + threadIdx.x;
    if (i < N) { g_deg[i] = 0; g_cursor[i] = 0; }
    if (blockIdx.x == 0 && threadIdx.x == 0) {
        const int* p = (const int*)ei;
        int zeros = 0;
#pragma unroll
        for (int j = 0; j < 32; j++)
            if (p[2 * j + 1] == 0) zeros++;
        g_is64 = (zeros >= 30) ? 1 : 0;
    }
}

// ---- repack weights into k-grouped float4 layout (tiny) ----
__global__ void repack_kernel(const float* __restrict__ W1, const float* __restrict__ Wr1,
                              const float* __restrict__ W2, const float* __restrict__ Wr2) {
    const int n1 = NDEG * 32 * 32;  // 11264
    const int n2 = NDEG * 8 * 64;   // 5632
    int t = blockIdx.x * blockDim.x + threadIdx.x;
    if (t < 2 * n1) {
        int u = (t < n1) ? t : t - n1;
        const float* src = (t < n1) ? W1 : Wr1;
        float4* dst = (t < n1) ? g_W1p : g_Wr1p;
        int d = u / 1024, r = u % 1024, g = r / 32, o = r % 32;
        int b = d * F_IN * F_HID + (4 * g) * F_HID + o;
        dst[u] = make_float4(src[b], src[b + F_HID], src[b + 2 * F_HID], src[b + 3 * F_HID]);
    } else if (t < 2 * n1 + 2 * n2) {
        int v = t - 2 * n1;
        int u = (v < n2) ? v : v - n2;
        const float* src = (v < n2) ? W2 : Wr2;
        float4* dst = (v < n2) ? g_W2p : g_Wr2p;
        int d = u / 512, r = u % 512, g = r / 64, o = r % 64;
        int b = d * F_HID * F_OUT + (4 * g) * F_OUT + o;
        dst[u] = make_float4(src[b], src[b + F_OUT], src[b + 2 * F_OUT], src[b + 3 * F_OUT]);
    }
}

// ---- degree count ----
__global__ void count_kernel(const void* __restrict__ ei, int E, int N) {
    int e = blockIdx.x * blockDim.x + threadIdx.x;
    if (e >= E) return;
    int dst = edge_at(ei, (long long)E + e);
    if ((unsigned)dst >= (unsigned)N) return;
    atomicAdd(&g_deg[dst], 1);
}

// ---- exclusive scan of g_deg -> g_rowstart (3 stages) ----
__global__ void scan1_kernel(int N) {
    __shared__ int s[1024];
    int i = blockIdx.x * 1024 + threadIdx.x;
    int v = (i < N) ? g_deg[i] : 0;
    s[threadIdx.x] = v;
    __syncthreads();
    for (int off = 1; off < 1024; off <<= 1) {
        int t = (threadIdx.x >= off) ? s[threadIdx.x - off] : 0;
        __syncthreads();
        s[threadIdx.x] += t;
        __syncthreads();
    }
    if (i < N) g_rowstart[i] = s[threadIdx.x] - v;
    if (threadIdx.x == 1023) g_bsum[blockIdx.x] = s[1023];
}

__global__ void scan2_kernel(int nb) {
    __shared__ int s[256];
    int v = (threadIdx.x < nb) ? g_bsum[threadIdx.x] : 0;
    s[threadIdx.x] = v;
    __syncthreads();
    for (int off = 1; off < 256; off <<= 1) {
        int t = (threadIdx.x >= off) ? s[threadIdx.x - off] : 0;
        __syncthreads();
        s[threadIdx.x] += t;
        __syncthreads();
    }
    if (threadIdx.x < nb) g_bsum[threadIdx.x] = s[threadIdx.x] - v;
}

__global__ void scan3_kernel(int N) {
    int i = blockIdx.x * blockDim.x + threadIdx.x;
    if (i < N) g_rowstart[i] += g_bsum[i >> 10];
}

// ---- CSR fill ----
__global__ void fill_kernel(const void* __restrict__ ei, int E, int N) {
    int e = blockIdx.x * blockDim.x + threadIdx.x;
    if (e >= E) return;
    int src = edge_at(ei, e);
    int dst = edge_at(ei, (long long)E + e);
    if ((unsigned)dst >= (unsigned)N || (unsigned)src >= (unsigned)N) return;
    int pos = atomicAdd(&g_cursor[dst], 1);
    g_csrc[g_rowstart[dst] + pos] = src;
}

// ---- project1: P(n)=W1[10].x_n, R(n)=Wr1[10].x_n for ALL nodes.
//  8 warps = 8 nodes per block; warp w owns k-groups [4w,4w+4) (k-split,
//  8x weight amortization). Same FLOPs the old post-agg GEMV spent.
__global__ void project1_kernel(const float* __restrict__ x, int N) {
    __shared__ float sh_x[8][128];
    __shared__ float sh_pp[8][8][32];   // [warp][node][out]
    __shared__ float sh_pr[8][8][32];
    int warp = threadIdx.x >> 5, lane = threadIdx.x & 31;
    int base = blockIdx.x * 8;
    int n = base + warp;
    const float4* xv = (const float4*)x;

    ((float4*)&sh_x[warp][0])[lane] =
        (n < N) ? xv[(size_t)n * 32 + lane] : make_float4(0.f, 0.f, 0.f, 0.f);
    __syncthreads();

    float pp[8], pr[8];
#pragma unroll
    for (int i = 0; i < 8; i++) { pp[i] = 0.f; pr[i] = 0.f; }
    const float4* w1 = &g_W1p [MAXDEG * 1024 + lane];
    const float4* wr = &g_Wr1p[MAXDEG * 1024 + lane];
#pragma unroll
    for (int gg = 0; gg < 4; gg++) {
        int g = warp * 4 + gg;
        float4 a = w1[g * 32];
        float4 b = wr[g * 32];
#pragma unroll
        for (int i = 0; i < 8; i++) {
            float4 xx = *(const float4*)&sh_x[i][4 * g];
            pp[i] += xx.x * a.x + xx.y * a.y + xx.z * a.z + xx.w * a.w;
            pr[i] += xx.x * b.x + xx.y * b.y + xx.z * b.z + xx.w * b.w;
        }
    }
#pragma unroll
    for (int i = 0; i < 8; i++) { sh_pp[warp][i][lane] = pp[i]; sh_pr[warp][i][lane] = pr[i]; }
    __syncthreads();

    if (n < N) {
        float accp = 0.f, accr = 0.f;
#pragma unroll
        for (int w = 0; w < 8; w++) { accp += sh_pp[w][warp][lane]; accr += sh_pr[w][warp][lane]; }
        g_p1[(size_t)n * F_HID + lane] = accp;
        g_r1[(size_t)n * F_HID + lane] = accr;
    }
}

// ---- agg1: warp per node.
//  dc==10 (96%): aggregate 32-float P rows (128B/edge, 4x less traffic) + R + bias.
//  dc!=10: fall back to gather-x + full GEMV with bucket-dc weights.
__global__ void agg1_kernel(const float* __restrict__ x, const float* __restrict__ b1, int N) {
    __shared__ float sh[8][256];  // fallback only: h[128] | x[128]
    int warp = threadIdx.x >> 5, lane = threadIdx.x & 31;
    int n = blockIdx.x * 8 + warp;
    if (n >= N) return;
    int d = g_deg[n];
    int start = g_rowstart[n];

    if (d >= MAXDEG) {
        float acc = g_r1[(size_t)n * F_HID + lane] + b1[MAXDEG * F_HID + lane];
        int k = 0;
        for (; k + 8 <= d; k += 8) {
            int s0 = g_csrc[start + k + 0];
            int s1 = g_csrc[start + k + 1];
            int s2 = g_csrc[start + k + 2];
            int s3 = g_csrc[start + k + 3];
            int s4 = g_csrc[start + k + 4];
            int s5 = g_csrc[start + k + 5];
            int s6 = g_csrc[start + k + 6];
            int s7 = g_csrc[start + k + 7];
            float v0 = g_p1[(size_t)s0 * F_HID + lane];
            float v1 = g_p1[(size_t)s1 * F_HID + lane];
            float v2 = g_p1[(size_t)s2 * F_HID + lane];
            float v3 = g_p1[(size_t)s3 * F_HID + lane];
            float v4 = g_p1[(size_t)s4 * F_HID + lane];
            float v5 = g_p1[(size_t)s5 * F_HID + lane];
            float v6 = g_p1[(size_t)s6 * F_HID + lane];
            float v7 = g_p1[(size_t)s7 * F_HID + lane];
            acc += ((v0 + v1) + (v2 + v3)) + ((v4 + v5) + (v6 + v7));
        }
        for (; k < d; k++) {
            int s = g_csrc[start + k];
            acc += g_p1[(size_t)s * F_HID + lane];
        }
        g_h2[(size_t)n * F_HID + lane] = fmaxf(acc, 0.f);
    } else {
        // rare path: gather x rows, GEMV with bucket-d weights
        const float4* xv = (const float4*)x;
        float4 hacc = make_float4(0.f, 0.f, 0.f, 0.f);
        for (int k = 0; k < d; k++) {
            int s = g_csrc[start + k];
            float4 v = xv[(size_t)s * 32 + lane];
            hacc.x += v.x; hacc.y += v.y; hacc.z += v.z; hacc.w += v.w;
        }
        ((float4*)&sh[warp][0])[lane]   = hacc;
        ((float4*)&sh[warp][128])[lane] = xv[(size_t)n * 32 + lane];
        __syncwarp();
        float acc = b1[d * F_HID + lane];
        const float4* w1 = &g_W1p [d * 1024 + lane];
        const float4* wr = &g_Wr1p[d * 1024 + lane];
#pragma unroll 8
        for (int g = 0; g < 32; g++) {
            float4 hh = *(const float4*)&sh[warp][4 * g];
            float4 xx = *(const float4*)&sh[warp][128 + 4 * g];
            float4 a = w1[g * 32];
            float4 b = wr[g * 32];
            acc += hh.x * a.x + hh.y * a.y + hh.z * a.z + hh.w * a.w
                 + xx.x * b.x + xx.y * b.y + xx.z * b.z + xx.w * b.w;
        }
        g_h2[(size_t)n * F_HID + lane] = fmaxf(acc, 0.f);
    }
}

// ---- fused layer-2 (unchanged from round 15): gather in 32-dim then k-split GEMV ----
__global__ void layer2_kernel(const float* __restrict__ b2, float* __restrict__ out, int N) {
    __shared__ float sh_act[8][64];        // per node: agg[32] | h2[32]
    __shared__ float sh_p0[8][8][32];
    __shared__ float sh_p1[8][8][32];
    int warp = threadIdx.x >> 5, lane = threadIdx.x & 31;
    int base = blockIdx.x * 8;
    int n = base + warp;

    int dc = -1;
    if (n < N) {
        int d = g_deg[n];
        int start = g_rowstart[n];
        float hacc = 0.f;
        int k = 0;
        for (; k + 8 <= d; k += 8) {
            int s0 = g_csrc[start + k + 0];
            int s1 = g_csrc[start + k + 1];
            int s2 = g_csrc[start + k + 2];
            int s3 = g_csrc[start + k + 3];
            int s4 = g_csrc[start + k + 4];
            int s5 = g_csrc[start + k + 5];
            int s6 = g_csrc[start + k + 6];
            int s7 = g_csrc[start + k + 7];
            float v0 = g_h2[(size_t)s0 * F_HID + lane];
            float v1 = g_h2[(size_t)s1 * F_HID + lane];
            float v2 = g_h2[(size_t)s2 * F_HID + lane];
            float v3 = g_h2[(size_t)s3 * F_HID + lane];
            float v4 = g_h2[(size_t)s4 * F_HID + lane];
            float v5 = g_h2[(size_t)s5 * F_HID + lane];
            float v6 = g_h2[(size_t)s6 * F_HID + lane];
            float v7 = g_h2[(size_t)s7 * F_HID + lane];
            hacc += ((v0 + v1) + (v2 + v3)) + ((v4 + v5) + (v6 + v7));
        }
        for (; k < d; k++) {
            int s = g_csrc[start + k];
            hacc += g_h2[(size_t)s * F_HID + lane];
        }
        sh_act[warp][lane]      = hacc;
        sh_act[warp][32 + lane] = g_h2[(size_t)n * F_HID + lane];
        dc = min(d, MAXDEG);
    } else {
        sh_act[warp][lane]      = 0.f;
        sh_act[warp][32 + lane] = 0.f;
    }
    __syncthreads();

    {
        float p0[8], p1[8];
        int g = warp;
        const float4* w2  = &g_W2p [MAXDEG * 512];
        const float4* wr2 = &g_Wr2p[MAXDEG * 512];
        float4 a0 = w2 [g * 64 + lane];
        float4 a1 = w2 [g * 64 + 32 + lane];
        float4 r0 = wr2[g * 64 + lane];
        float4 r1 = wr2[g * 64 + 32 + lane];
#pragma unroll
        for (int i = 0; i < 8; i++) {
            float4 hh = *(const float4*)&sh_act[i][4 * g];
            float4 xx = *(const float4*)&sh_act[i][32 + 4 * g];
            p0[i] = hh.x * a0.x + hh.y * a0.y + hh.z * a0.z + hh.w * a0.w
                  + xx.x * r0.x + xx.y * r0.y + xx.z * r0.z + xx.w * r0.w;
            p1[i] = hh.x * a1.x + hh.y * a1.y + hh.z * a1.z + hh.w * a1.w
                  + xx.x * r1.x + xx.y * r1.y + xx.z * r1.z + xx.w * r1.w;
        }
#pragma unroll
        for (int i = 0; i < 8; i++) { sh_p0[warp][i][lane] = p0[i]; sh_p1[warp][i][lane] = p1[i]; }
    }
    __syncthreads();

    if (dc >= 0 && dc != MAXDEG) {
        float acc0 = b2[dc * F_OUT + lane];
        float acc1 = b2[dc * F_OUT + 32 + lane];
        const float4* w2  = &g_W2p [dc * 512];
        const float4* wr2 = &g_Wr2p[dc * 512];
#pragma unroll
        for (int g = 0; g < 8; g++) {
            float4 hh = *(const float4*)&sh_act[warp][4 * g];
            float4 xx = *(const float4*)&sh_act[warp][32 + 4 * g];
            float4 a0 = w2 [g * 64 + lane];
            float4 a1 = w2 [g * 64 + 32 + lane];
            float4 r0 = wr2[g * 64 + lane];
            float4 r1 = wr2[g * 64 + 32 + lane];
            acc0 += hh.x * a0.x + hh.y * a0.y + hh.z * a0.z + hh.w * a0.w
                  + xx.x * r0.x + xx.y * r0.y + xx.z * r0.z + xx.w * r0.w;
            acc1 += hh.x * a1.x + hh.y * a1.y + hh.z * a1.z + hh.w * a1.w
                  + xx.x * r1.x + xx.y * r1.y + xx.z * r1.z + xx.w * r1.w;
        }
        out[(size_t)n * F_OUT + lane]      = acc0;
        out[(size_t)n * F_OUT + 32 + lane] = acc1;
    }

    if (dc == MAXDEG) {
        float acc0 = b2[MAXDEG * F_OUT + lane];
        float acc1 = b2[MAXDEG * F_OUT + 32 + lane];
#pragma unroll
        for (int w = 0; w < 8; w++) { acc0 += sh_p0[w][warp][lane]; acc1 += sh_p1[w][warp][lane]; }
        out[(size_t)n * F_OUT + lane]      = acc0;
        out[(size_t)n * F_OUT + 32 + lane] = acc1;
    }
}

extern "C" void kernel_launch(void* const* d_in, const int* in_sizes, int n_in,
                              void* d_out, int out_size) {
    const float* x   = (const float*)d_in[0];
    const void*  ei  = d_in[1];
    const float* W1  = (const float*)d_in[2];
    const float* b1  = (const float*)d_in[3];
    const float* Wr1 = (const float*)d_in[4];
    const float* W2  = (const float*)d_in[5];
    const float* b2  = (const float*)d_in[6];
    const float* Wr2 = (const float*)d_in[7];

    int N = in_sizes[0] / F_IN;
    int E = in_sizes[1] / 2;
    int nb = (N + 1023) / 1024;

    zero_detect_kernel<<<(N + 255) / 256, 256>>>(ei, N);
    int repack_threads = 2 * (NDEG * 32 * 32) + 2 * (NDEG * 8 * 64);
    repack_kernel<<<(repack_threads + 255) / 256, 256>>>(W1, Wr1, W2, Wr2);
    count_kernel<<<(E + 255) / 256, 256>>>(ei, E, N);
    scan1_kernel<<<nb, 1024>>>(N);
    scan2_kernel<<<1, 256>>>(nb);
    scan3_kernel<<<(N + 255) / 256, 256>>>(N);
    fill_kernel<<<(E + 255) / 256, 256>>>(ei, E, N);

    project1_kernel<<<(N + 7) / 8, 256>>>(x, N);
    agg1_kernel<<<(N + 7) / 8, 256>>>(x, b1, N);
    layer2_kernel<<<(N + 7) / 8, 256>>>(b2, (float*)d_out, N);
}

// round 17
// speedup vs baseline: 1.6953x; 1.0277x over previous
#include <cuda_runtime.h>
#include <cuda_bf16.h>
#include <cstdint>

#define F_IN   128
#define F_HID  32
#define F_OUT  64
#define NDEG   11
#define MAXDEG 10
#define MAXN   100000
#define MAXE   1600000

// ---- scratch (__device__ globals; no allocation allowed) ----
__device__ int    g_is64;
__device__ int    g_deg[MAXN];
__device__ int    g_rowstart[MAXN];
__device__ int    g_cursor[MAXN];
__device__ int    g_csrc[MAXE];
__device__ int    g_bsum[256];
__device__ float  g_p1[MAXN * F_HID];    // W1[10] . x_n   (projected neighbors)
__device__ float  g_r1[MAXN * F_HID];    // Wr1[10] . x_n  (projected root)
__device__ float  g_h2[MAXN * F_HID];    // relu(layer-1 out)
// packed weights: [d][k/4][o] as float4 over the 4 k-components
__device__ float4 g_W1p [NDEG * 32 * 32];
__device__ float4 g_Wr1p[NDEG * 32 * 32];
__device__ float4 g_W2p [NDEG * 8  * 64];
__device__ float4 g_Wr2p[NDEG * 8  * 64];

// edge_index may be int32 (jax default) or int64 (x64 enabled). Branch on flag.
__device__ __forceinline__ int edge_at(const void* ei, long long pos) {
    if (g_is64) return (int)((const long long*)ei)[pos];
    return ((const int*)ei)[pos];
}

// ---- zero + dtype sniff fused ----
__global__ void zero_detect_kernel(const void* ei, int N) {
    int i = blockIdx.x * blockDim.x + threadIdx.x;
    if (i < N) { g_deg[i] = 0; g_cursor[i] = 0; }
    if (blockIdx.x == 0 && threadIdx.x == 0) {
        const int* p = (const int*)ei;
        int zeros = 0;
#pragma unroll
        for (int j = 0; j < 32; j++)
            if (p[2 * j + 1] == 0) zeros++;
        g_is64 = (zeros >= 30) ? 1 : 0;
    }
}

// ---- repack weights into k-grouped float4 layout (tiny) ----
__global__ void repack_kernel(const float* __restrict__ W1, const float* __restrict__ Wr1,
                              const float* __restrict__ W2, const float* __restrict__ Wr2) {
    const int n1 = NDEG * 32 * 32;  // 11264
    const int n2 = NDEG * 8 * 64;   // 5632
    int t = blockIdx.x * blockDim.x + threadIdx.x;
    if (t < 2 * n1) {
        int u = (t < n1) ? t : t - n1;
        const float* src = (t < n1) ? W1 : Wr1;
        float4* dst = (t < n1) ? g_W1p : g_Wr1p;
        int d = u / 1024, r = u % 1024, g = r / 32, o = r % 32;
        int b = d * F_IN * F_HID + (4 * g) * F_HID + o;
        dst[u] = make_float4(src[b], src[b + F_HID], src[b + 2 * F_HID], src[b + 3 * F_HID]);
    } else if (t < 2 * n1 + 2 * n2) {
        int v = t - 2 * n1;
        int u = (v < n2) ? v : v - n2;
        const float* src = (v < n2) ? W2 : Wr2;
        float4* dst = (v < n2) ? g_W2p : g_Wr2p;
        int d = u / 512, r = u % 512, g = r / 64, o = r % 64;
        int b = d * F_HID * F_OUT + (4 * g) * F_OUT + o;
        dst[u] = make_float4(src[b], src[b + F_OUT], src[b + 2 * F_OUT], src[b + 3 * F_OUT]);
    }
}

// ---- degree count ----
__global__ void count_kernel(const void* __restrict__ ei, int E, int N) {
    int e = blockIdx.x * blockDim.x + threadIdx.x;
    if (e >= E) return;
    int dst = edge_at(ei, (long long)E + e);
    if ((unsigned)dst >= (unsigned)N) return;
    atomicAdd(&g_deg[dst], 1);
}

// ---- exclusive scan of g_deg -> g_rowstart (3 stages) ----
__global__ void scan1_kernel(int N) {
    __shared__ int s[1024];
    int i = blockIdx.x * 1024 + threadIdx.x;
    int v = (i < N) ? g_deg[i] : 0;
    s[threadIdx.x] = v;
    __syncthreads();
    for (int off = 1; off < 1024; off <<= 1) {
        int t = (threadIdx.x >= off) ? s[threadIdx.x - off] : 0;
        __syncthreads();
        s[threadIdx.x] += t;
        __syncthreads();
    }
    if (i < N) g_rowstart[i] = s[threadIdx.x] - v;
    if (threadIdx.x == 1023) g_bsum[blockIdx.x] = s[1023];
}

__global__ void scan2_kernel(int nb) {
    __shared__ int s[256];
    int v = (threadIdx.x < nb) ? g_bsum[threadIdx.x] : 0;
    s[threadIdx.x] = v;
    __syncthreads();
    for (int off = 1; off < 256; off <<= 1) {
        int t = (threadIdx.x >= off) ? s[threadIdx.x - off] : 0;
        __syncthreads();
        s[threadIdx.x] += t;
        __syncthreads();
    }
    if (threadIdx.x < nb) g_bsum[threadIdx.x] = s[threadIdx.x] - v;
}

__global__ void scan3_kernel(int N) {
    int i = blockIdx.x * blockDim.x + threadIdx.x;
    if (i < N) g_rowstart[i] += g_bsum[i >> 10];
}

// ---- CSR fill ----
__global__ void fill_kernel(const void* __restrict__ ei, int E, int N) {
    int e = blockIdx.x * blockDim.x + threadIdx.x;
    if (e >= E) return;
    int src = edge_at(ei, e);
    int dst = edge_at(ei, (long long)E + e);
    if ((unsigned)dst >= (unsigned)N || (unsigned)src >= (unsigned)N) return;
    int pos = atomicAdd(&g_cursor[dst], 1);
    g_csrc[g_rowstart[dst] + pos] = src;
}

// ---- project1: P(n)=W1[10].x_n, R(n)=Wr1[10].x_n for ALL nodes (k-split, 8x amortized) ----
__global__ void project1_kernel(const float* __restrict__ x, int N) {
    __shared__ float sh_x[8][128];
    __shared__ float sh_pp[8][8][32];   // [warp][node][out]
    __shared__ float sh_pr[8][8][32];
    int warp = threadIdx.x >> 5, lane = threadIdx.x & 31;
    int base = blockIdx.x * 8;
    int n = base + warp;
    const float4* xv = (const float4*)x;

    ((float4*)&sh_x[warp][0])[lane] =
        (n < N) ? xv[(size_t)n * 32 + lane] : make_float4(0.f, 0.f, 0.f, 0.f);
    __syncthreads();

    float pp[8], pr[8];
#pragma unroll
    for (int i = 0; i < 8; i++) { pp[i] = 0.f; pr[i] = 0.f; }
    const float4* w1 = &g_W1p [MAXDEG * 1024 + lane];
    const float4* wr = &g_Wr1p[MAXDEG * 1024 + lane];
#pragma unroll
    for (int gg = 0; gg < 4; gg++) {
        int g = warp * 4 + gg;
        float4 a = w1[g * 32];
        float4 b = wr[g * 32];
#pragma unroll
        for (int i = 0; i < 8; i++) {
            float4 xx = *(const float4*)&sh_x[i][4 * g];
            pp[i] += xx.x * a.x + xx.y * a.y + xx.z * a.z + xx.w * a.w;
            pr[i] += xx.x * b.x + xx.y * b.y + xx.z * b.z + xx.w * b.w;
        }
    }
#pragma unroll
    for (int i = 0; i < 8; i++) { sh_pp[warp][i][lane] = pp[i]; sh_pr[warp][i][lane] = pr[i]; }
    __syncthreads();

    if (n < N) {
        float accp = 0.f, accr = 0.f;
#pragma unroll
        for (int w = 0; w < 8; w++) { accp += sh_pp[w][warp][lane]; accr += sh_pr[w][warp][lane]; }
        g_p1[(size_t)n * F_HID + lane] = accp;
        g_r1[(size_t)n * F_HID + lane] = accr;
    }
}

// ---- agg1: warp per node; dc==10 aggregates projected P rows; else fallback GEMV ----
__global__ void agg1_kernel(const float* __restrict__ x, const float* __restrict__ b1, int N) {
    __shared__ float sh[8][256];  // fallback only: h[128] | x[128]
    int warp = threadIdx.x >> 5, lane = threadIdx.x & 31;
    int n = blockIdx.x * 8 + warp;
    if (n >= N) return;
    int d = g_deg[n];
    int start = g_rowstart[n];

    if (d >= MAXDEG) {
        float acc = g_r1[(size_t)n * F_HID + lane] + b1[MAXDEG * F_HID + lane];
        int k = 0;
        for (; k + 8 <= d; k += 8) {
            int s0 = g_csrc[start + k + 0];
            int s1 = g_csrc[start + k + 1];
            int s2 = g_csrc[start + k + 2];
            int s3 = g_csrc[start + k + 3];
            int s4 = g_csrc[start + k + 4];
            int s5 = g_csrc[start + k + 5];
            int s6 = g_csrc[start + k + 6];
            int s7 = g_csrc[start + k + 7];
            float v0 = g_p1[(size_t)s0 * F_HID + lane];
            float v1 = g_p1[(size_t)s1 * F_HID + lane];
            float v2 = g_p1[(size_t)s2 * F_HID + lane];
            float v3 = g_p1[(size_t)s3 * F_HID + lane];
            float v4 = g_p1[(size_t)s4 * F_HID + lane];
            float v5 = g_p1[(size_t)s5 * F_HID + lane];
            float v6 = g_p1[(size_t)s6 * F_HID + lane];
            float v7 = g_p1[(size_t)s7 * F_HID + lane];
            acc += ((v0 + v1) + (v2 + v3)) + ((v4 + v5) + (v6 + v7));
        }
        for (; k < d; k++) {
            int s = g_csrc[start + k];
            acc += g_p1[(size_t)s * F_HID + lane];
        }
        g_h2[(size_t)n * F_HID + lane] = fmaxf(acc, 0.f);
    } else {
        const float4* xv = (const float4*)x;
        float4 hacc = make_float4(0.f, 0.f, 0.f, 0.f);
        for (int k = 0; k < d; k++) {
            int s = g_csrc[start + k];
            float4 v = xv[(size_t)s * 32 + lane];
            hacc.x += v.x; hacc.y += v.y; hacc.z += v.z; hacc.w += v.w;
        }
        ((float4*)&sh[warp][0])[lane]   = hacc;
        ((float4*)&sh[warp][128])[lane] = xv[(size_t)n * 32 + lane];
        __syncwarp();
        float acc = b1[d * F_HID + lane];
        const float4* w1 = &g_W1p [d * 1024 + lane];
        const float4* wr = &g_Wr1p[d * 1024 + lane];
#pragma unroll 8
        for (int g = 0; g < 32; g++) {
            float4 hh = *(const float4*)&sh[warp][4 * g];
            float4 xx = *(const float4*)&sh[warp][128 + 4 * g];
            float4 a = w1[g * 32];
            float4 b = wr[g * 32];
            acc += hh.x * a.x + hh.y * a.y + hh.z * a.z + hh.w * a.w
                 + xx.x * b.x + xx.y * b.y + xx.z * b.z + xx.w * b.w;
        }
        g_h2[(size_t)n * F_HID + lane] = fmaxf(acc, 0.f);
    }
}

// ---- fused layer-2: gather in 32-dim then k-split GEMV ----
__global__ void layer2_kernel(const float* __restrict__ b2, float* __restrict__ out, int N) {
    __shared__ float sh_act[8][64];        // per node: agg[32] | h2[32]
    __shared__ float sh_p0[8][8][32];
    __shared__ float sh_p1[8][8][32];
    int warp = threadIdx.x >> 5, lane = threadIdx.x & 31;
    int base = blockIdx.x * 8;
    int n = base + warp;

    int dc = -1;
    if (n < N) {
        int d = g_deg[n];
        int start = g_rowstart[n];
        float hacc = 0.f;
        int k = 0;
        for (; k + 8 <= d; k += 8) {
            int s0 = g_csrc[start + k + 0];
            int s1 = g_csrc[start + k + 1];
            int s2 = g_csrc[start + k + 2];
            int s3 = g_csrc[start + k + 3];
            int s4 = g_csrc[start + k + 4];
            int s5 = g_csrc[start + k + 5];
            int s6 = g_csrc[start + k + 6];
            int s7 = g_csrc[start + k + 7];
            float v0 = g_h2[(size_t)s0 * F_HID + lane];
            float v1 = g_h2[(size_t)s1 * F_HID + lane];
            float v2 = g_h2[(size_t)s2 * F_HID + lane];
            float v3 = g_h2[(size_t)s3 * F_HID + lane];
            float v4 = g_h2[(size_t)s4 * F_HID + lane];
            float v5 = g_h2[(size_t)s5 * F_HID + lane];
            float v6 = g_h2[(size_t)s6 * F_HID + lane];
            float v7 = g_h2[(size_t)s7 * F_HID + lane];
            hacc += ((v0 + v1) + (v2 + v3)) + ((v4 + v5) + (v6 + v7));
        }
        for (; k < d; k++) {
            int s = g_csrc[start + k];
            hacc += g_h2[(size_t)s * F_HID + lane];
        }
        sh_act[warp][lane]      = hacc;
        sh_act[warp][32 + lane] = g_h2[(size_t)n * F_HID + lane];
        dc = min(d, MAXDEG);
    } else {
        sh_act[warp][lane]      = 0.f;
        sh_act[warp][32 + lane] = 0.f;
    }
    __syncthreads();

    {
        float p0[8], p1[8];
        int g = warp;
        const float4* w2  = &g_W2p [MAXDEG * 512];
        const float4* wr2 = &g_Wr2p[MAXDEG * 512];
        float4 a0 = w2 [g * 64 + lane];
        float4 a1 = w2 [g * 64 + 32 + lane];
        float4 r0 = wr2[g * 64 + lane];
        float4 r1 = wr2[g * 64 + 32 + lane];
#pragma unroll
        for (int i = 0; i < 8; i++) {
            float4 hh = *(const float4*)&sh_act[i][4 * g];
            float4 xx = *(const float4*)&sh_act[i][32 + 4 * g];
            p0[i] = hh.x * a0.x + hh.y * a0.y + hh.z * a0.z + hh.w * a0.w
                  + xx.x * r0.x + xx.y * r0.y + xx.z * r0.z + xx.w * r0.w;
            p1[i] = hh.x * a1.x + hh.y * a1.y + hh.z * a1.z + hh.w * a1.w
                  + xx.x * r1.x + xx.y * r1.y + xx.z * r1.z + xx.w * r1.w;
        }
#pragma unroll
        for (int i = 0; i < 8; i++) { sh_p0[warp][i][lane] = p0[i]; sh_p1[warp][i][lane] = p1[i]; }
    }
    __syncthreads();

    if (dc >= 0 && dc != MAXDEG) {
        float acc0 = b2[dc * F_OUT + lane];
        float acc1 = b2[dc * F_OUT + 32 + lane];
        const float4* w2  = &g_W2p [dc * 512];
        const float4* wr2 = &g_Wr2p[dc * 512];
#pragma unroll
        for (int g = 0; g < 8; g++) {
            float4 hh = *(const float4*)&sh_act[warp][4 * g];
            float4 xx = *(const float4*)&sh_act[warp][32 + 4 * g];
            float4 a0 = w2 [g * 64 + lane];
            float4 a1 = w2 [g * 64 + 32 + lane];
            float4 r0 = wr2[g * 64 + lane];
            float4 r1 = wr2[g * 64 + 32 + lane];
            acc0 += hh.x * a0.x + hh.y * a0.y + hh.z * a0.z + hh.w * a0.w
                  + xx.x * r0.x + xx.y * r0.y + xx.z * r0.z + xx.w * r0.w;
            acc1 += hh.x * a1.x + hh.y * a1.y + hh.z * a1.z + hh.w * a1.w
                  + xx.x * r1.x + xx.y * r1.y + xx.z * r1.z + xx.w * r1.w;
        }
        out[(size_t)n * F_OUT + lane]      = acc0;
        out[(size_t)n * F_OUT + 32 + lane] = acc1;
    }

    if (dc == MAXDEG) {
        float acc0 = b2[MAXDEG * F_OUT + lane];
        float acc1 = b2[MAXDEG * F_OUT + 32 + lane];
#pragma unroll
        for (int w = 0; w < 8; w++) { acc0 += sh_p0[w][warp][lane]; acc1 += sh_p1[w][warp][lane]; }
        out[(size_t)n * F_OUT + lane]      = acc0;
        out[(size_t)n * F_OUT + 32 + lane] = acc1;
    }
}

extern "C" void kernel_launch(void* const* d_in, const int* in_sizes, int n_in,
                              void* d_out, int out_size) {
    const float* x   = (const float*)d_in[0];
    const void*  ei  = d_in[1];
    const float* W1  = (const float*)d_in[2];
    const float* b1  = (const float*)d_in[3];
    const float* Wr1 = (const float*)d_in[4];
    const float* W2  = (const float*)d_in[5];
    const float* b2  = (const float*)d_in[6];
    const float* Wr2 = (const float*)d_in[7];

    int N = in_sizes[0] / F_IN;
    int E = in_sizes[1] / 2;
    int nb = (N + 1023) / 1024;

    // Fork/join: project1 (FFMA-bound) overlaps the CSR-build chain (atomics/LSU-bound).
    cudaStream_t s1;
    cudaEvent_t eA, eB;
    cudaStreamCreateWithFlags(&s1, cudaStreamNonBlocking);
    cudaEventCreateWithFlags(&eA, cudaEventDisableTiming);
    cudaEventCreateWithFlags(&eB, cudaEventDisableTiming);

    zero_detect_kernel<<<(N + 255) / 256, 256>>>(ei, N);
    int repack_threads = 2 * (NDEG * 32 * 32) + 2 * (NDEG * 8 * 64);
    repack_kernel<<<(repack_threads + 255) / 256, 256>>>(W1, Wr1, W2, Wr2);
    cudaEventRecord(eA, 0);

    // branch B: projection (needs only repacked weights + x)
    cudaStreamWaitEvent(s1, eA, 0);
    project1_kernel<<<(N + 7) / 8, 256, 0, s1>>>(x, N);
    cudaEventRecord(eB, s1);

    // branch A: CSR build (needs zeroed deg/cursor + is64)
    count_kernel<<<(E + 255) / 256, 256>>>(ei, E, N);
    scan1_kernel<<<nb, 1024>>>(N);
    scan2_kernel<<<1, 256>>>(nb);
    scan3_kernel<<<(N + 255) / 256, 256>>>(N);
    fill_kernel<<<(E + 255) / 256, 256>>>(ei, E, N);

    // join: agg1 needs CSR (branch A) + projections (branch B)
    cudaStreamWaitEvent(0, eB, 0);
    agg1_kernel<<<(N + 7) / 8, 256>>>(x, b1, N);
    layer2_kernel<<<(N + 7) / 8, 256>>>(b2, (float*)d_out, N);

    cudaEventDestroy(eA);
    cudaEventDestroy(eB);
    cudaStreamDestroy(s1);
}